// round 12
// baseline (speedup 1.0000x reference)
#include <cuda_runtime.h>
#include <cuda_bf16.h>
#include <cstdint>

// Problem constants (match reference_code)
#define NV       1000000
#define NE       3000000
#define IMG_H    1024
#define IMG_W    1024
#define HW       (IMG_H * IMG_W)       // 1048576
#define MAX_DEPTH 10.0f
#define CREGU    2000.0f

#define B        256
#define NQ       (NV / 4)                      // 250000 vertex quads
#define PRE_BLOCKS   ((HW / 4) / B)            // 1024
#define PROJ_BLOCKS  ((NQ + B - 1) / B)        // 977
#define EDGE_BLOCKS  ((NE / 2 + B - 1) / B)    // 5860

// ---------------- scratch (device globals; zero-initialized at load) --------
__device__ float    g_depth[HW];      // 4 MB    scatter-min target
__device__ float4   g_dv4[NV];        // 16 MB   {dvx, dvy, dvz, 0}
__device__ float4   g_neigh4[NV];     // 16 MB   {nx, ny, nz, deg}
__device__ double   g_sums[3];        // vertex component sums (self-zeroing)
__device__ double   g_acc;            // total energy accumulator (self-zeroing)
__device__ unsigned g_done;           // last-block counter (self-zeroing)

// ---------------- float block reduce (shared) --------------------------------
__device__ __forceinline__ float block_reduce_f(float v) {
    __shared__ float sh[B];
    int t = threadIdx.x;
    sh[t] = v;
    __syncthreads();
    for (int s = blockDim.x >> 1; s > 32; s >>= 1) {
        if (t < s) sh[t] += sh[t + s];
        __syncthreads();
    }
    if (t < 32) {
        float x = sh[t] + sh[t + 32];
        #pragma unroll
        for (int o = 16; o > 0; o >>= 1)
            x += __shfl_down_sync(0xFFFFFFFFu, x, o);
        if (t == 0) sh[0] = x;
    }
    __syncthreads();
    return sh[0];
}

// ---------------- K1: depth fill + vertex mean partials ----------------------
__global__ void k_mean_fill(const float4* __restrict__ verts4) {
    cudaTriggerProgrammaticLaunchCompletion();   // let K2 start prefetching
    int i = blockIdx.x * blockDim.x + threadIdx.x;   // < 262144
    ((float4*)g_depth)[i] = make_float4(MAX_DEPTH, MAX_DEPTH, MAX_DEPTH, MAX_DEPTH);

    float sx = 0.0f, sy = 0.0f, sz = 0.0f;
    if (i < NQ) {
        float4 a = verts4[3 * i + 0];   // v0.x v0.y v0.z v1.x
        float4 b = verts4[3 * i + 1];   // v1.y v1.z v2.x v2.y
        float4 c = verts4[3 * i + 2];   // v2.z v3.x v3.y v3.z
        sx = a.x + a.w + b.z + c.y;
        sy = a.y + b.x + b.w + c.z;
        sz = a.z + b.y + c.x + c.w;
    }
    float bx = block_reduce_f(sx);
    __syncthreads();
    float by = block_reduce_f(sy);
    __syncthreads();
    float bz = block_reduce_f(sz);
    if (threadIdx.x == 0) {
        atomicAdd(&g_sums[0], (double)bx);
        atomicAdd(&g_sums[1], (double)by);
        atomicAdd(&g_sums[2], (double)bz);
    }
}

// ---------------- K2: dv + neigh zero (pre-sync), project (post-sync) --------
// The dv/neigh phase touches nothing K1 writes -> runs overlapped with K1.
__global__ void k_pre_proj(const float4* __restrict__ verts4,
                           const float4* __restrict__ vref4,
                           const float* __restrict__ quat,
                           const float* __restrict__ trans,
                           const float* __restrict__ intr,
                           const float* __restrict__ extr) {
    cudaTriggerProgrammaticLaunchCompletion();   // let K3 start prefetching
    int i = blockIdx.x * blockDim.x + threadIdx.x;   // < 250000
    if (i >= NQ) {
        cudaGridDependencySynchronize();
        return;
    }

    float4 a = verts4[3 * i + 0];
    float4 b = verts4[3 * i + 1];
    float4 c = verts4[3 * i + 2];
    float4 ra = vref4[3 * i + 0];
    float4 rb = vref4[3 * i + 1];
    float4 rc = vref4[3 * i + 2];

    g_dv4[4 * i + 0] = make_float4(a.x - ra.x, a.y - ra.y, a.z - ra.z, 0.0f);
    g_dv4[4 * i + 1] = make_float4(a.w - ra.w, b.x - rb.x, b.y - rb.y, 0.0f);
    g_dv4[4 * i + 2] = make_float4(b.z - rb.z, b.w - rb.w, c.x - rc.x, 0.0f);
    g_dv4[4 * i + 3] = make_float4(c.y - rc.y, c.z - rc.z, c.w - rc.w, 0.0f);
    float4 z4 = make_float4(0.0f, 0.0f, 0.0f, 0.0f);
    g_neigh4[4 * i + 0] = z4;
    g_neigh4[4 * i + 1] = z4;
    g_neigh4[4 * i + 2] = z4;
    g_neigh4[4 * i + 3] = z4;

    // ---- wait for K1: depth filled, mean sums complete ----
    cudaGridDependencySynchronize();

    float qx = quat[0], qy = quat[1], qz = quat[2], qw = quat[3];
    float qn = 1.0f / sqrtf(qx * qx + qy * qy + qz * qz + qw * qw);
    qx *= qn; qy *= qn; qz *= qn; qw *= qn;

    float mx = (float)(g_sums[0] / (double)NV);
    float my = (float)(g_sums[1] / (double)NV);
    float mz = (float)(g_sums[2] / (double)NV);

    float vxs[4] = {a.x, a.w, b.z, c.y};
    float vys[4] = {a.y, b.x, b.w, c.z};
    float vzs[4] = {a.z, b.y, c.x, c.w};

    #pragma unroll
    for (int k = 0; k < 4; k++) {
        float vx = vxs[k] - mx;
        float vy = vys[k] - my;
        float vz = vzs[k] - mz;

        // qrot: v + 2*(w*uv + uuv), uv = qv x v, uuv = qv x uv
        float uvx = qy * vz - qz * vy;
        float uvy = qz * vx - qx * vz;
        float uvz = qx * vy - qy * vx;
        float uuvx = qy * uvz - qz * uvy;
        float uuvy = qz * uvx - qx * uvz;
        float uuvz = qx * uvy - qy * uvx;
        float tx = vx + 2.0f * (qw * uvx + uuvx) + trans[0];
        float ty = vy + 2.0f * (qw * uvy + uuvy) + trans[1];
        float tz = vz + 2.0f * (qw * uvz + uuvz) + trans[2];

        // p_cam = E[:, :3] @ v_t + E[:, 3]   (extr row-major 3x4)
        float p0 = extr[0] * tx + extr[1] * ty + extr[2]  * tz + extr[3];
        float p1 = extr[4] * tx + extr[5] * ty + extr[6]  * tz + extr[7];
        float p2 = extr[8] * tx + extr[9] * ty + extr[10] * tz + extr[11];

        // proj = K @ p_cam (intr row-major 3x3)
        float pr0 = intr[0] * p0 + intr[1] * p1 + intr[2] * p2;
        float pr1 = intr[3] * p0 + intr[4] * p1 + intr[5] * p2;
        float pr2 = intr[6] * p0 + intr[7] * p1 + intr[8] * p2;

        float u = pr0 / pr2;
        float v = pr1 / pr2;

        float fx = rintf(u);                  // round half to even == jnp.round
        float fy = rintf(v);
        fx = fminf(fmaxf(fx, 0.0f), (float)(IMG_W - 1));
        fy = fminf(fmaxf(fy, 0.0f), (float)(IMG_H - 1));
        int flat = (int)fy * IMG_W + (int)fx;

        float zval = (p2 > 0.0f) ? p2 : MAX_DEPTH;   // DEPTH_SCALE = 1
        // zval > 0, so int-bitpattern min == float min
        atomicMin((int*)&g_depth[flat], __float_as_int(zval));
    }
}

// ---------------- K3: edge accumulation (prefetch indices pre-sync) ----------
__global__ void k_edge(const int4* __restrict__ edges2) {
    cudaTriggerProgrammaticLaunchCompletion();   // let K4 start prefetching
    int e = blockIdx.x * blockDim.x + threadIdx.x;   // < NE/2
    if (e >= NE / 2) {
        cudaGridDependencySynchronize();
        return;
    }
    int4 p = edges2[e];                   // pure input: overlaps K2

    // ---- wait for K2: dv4 / neigh4 ready ----
    cudaGridDependencySynchronize();

    float4 dv0 = g_dv4[p.y];
    float4 dv1 = g_dv4[p.w];
    asm volatile(
        "red.global.add.v4.f32 [%0], {%1, %2, %3, %4};"
        :: "l"(&g_neigh4[p.x]), "f"(dv0.x), "f"(dv0.y), "f"(dv0.z), "f"(1.0f)
        : "memory");
    asm volatile(
        "red.global.add.v4.f32 [%0], {%1, %2, %3, %4};"
        :: "l"(&g_neigh4[p.z]), "f"(dv1.x), "f"(dv1.y), "f"(dv1.z), "f"(1.0f)
        : "memory");
}

// ---------------- K4: energy + last-block finalize ---------------------------
// K3 completion implies K2 completion (all K3 threads synced on K2), so one
// sync covers both the depth (K2) and neigh (K3) dependencies.
__global__ void k_energy_final(const float4* __restrict__ hand4,
                               float* __restrict__ out) {
    int i = blockIdx.x * blockDim.x + threadIdx.x;   // < 262144
    float4 h = hand4[i];                  // pure input: overlaps K3

    cudaGridDependencySynchronize();

    float4 d = ((const float4*)g_depth)[i];
    float d0 = d.x - h.x, d1 = d.y - h.y, d2 = d.z - h.z, d3 = d.w - h.w;
    float local = d0 * d0 + d1 * d1 + d2 * d2 + d3 * d3;

    if (i < NQ) {
        #pragma unroll
        for (int k = 0; k < 4; k++) {
            float4 dv = g_dv4[4 * i + k];
            float4 nb = g_neigh4[4 * i + k];
            float dg = nb.w;
            float lx = dg * dv.x - nb.x;
            float ly = dg * dv.y - nb.y;
            float lz = dg * dv.z - nb.z;
            local += CREGU * (lx * lx + ly * ly + lz * lz);
        }
    }
    float b = block_reduce_f(local);
    if (threadIdx.x == 0) {
        atomicAdd(&g_acc, (double)b);
        __threadfence();
        unsigned t = atomicAdd(&g_done, 1u);
        if (t == gridDim.x - 1) {      // last block: finalize + re-zero
            out[0] = (float)g_acc;
            g_acc = 0.0;
            g_sums[0] = 0.0; g_sums[1] = 0.0; g_sums[2] = 0.0;
            g_done = 0u;
        }
    }
}

// ---------------- helper: launch with PDL attribute --------------------------
template <typename... Args>
static void launch_pdl(void (*kern)(Args...), dim3 grid, dim3 block,
                       Args... args) {
    cudaLaunchConfig_t cfg = {};
    cfg.gridDim = grid;
    cfg.blockDim = block;
    cfg.dynamicSmemBytes = 0;
    cfg.stream = 0;
    cudaLaunchAttribute attr[1];
    attr[0].id = cudaLaunchAttributeProgrammaticStreamSerialization;
    attr[0].val.programmaticStreamSerializationAllowed = 1;
    cfg.attrs = attr;
    cfg.numAttrs = 1;
    cudaLaunchKernelEx(&cfg, kern, args...);
}

// ---------------- launch -----------------------------------------------------
extern "C" void kernel_launch(void* const* d_in, const int* in_sizes, int n_in,
                              void* d_out, int out_size) {
    const float4* verts4 = (const float4*)d_in[0];
    const float4* vref4  = (const float4*)d_in[1];
    const float*  quat   = (const float*)d_in[2];
    const float*  trans  = (const float*)d_in[3];
    const float4* hand4  = (const float4*)d_in[4];
    const float*  intr   = (const float*)d_in[5];
    const float*  extr   = (const float*)d_in[6];
    const int4*   edges2 = (const int4*)d_in[7];
    float* out = (float*)d_out;

    k_mean_fill<<<PRE_BLOCKS, B>>>(verts4);
    launch_pdl(k_pre_proj, dim3(PROJ_BLOCKS), dim3(B),
               verts4, vref4, quat, trans, intr, extr);
    launch_pdl(k_edge, dim3(EDGE_BLOCKS), dim3(B), edges2);
    launch_pdl(k_energy_final, dim3(PRE_BLOCKS), dim3(B), hand4, out);
}

// round 13
// speedup vs baseline: 1.0053x; 1.0053x over previous
#include <cuda_runtime.h>
#include <cuda_bf16.h>
#include <cstdint>

// Problem constants (match reference_code)
#define NV       1000000
#define NE       3000000
#define IMG_H    1024
#define IMG_W    1024
#define HW       (IMG_H * IMG_W)       // 1048576
#define MAX_DEPTH 10.0f
#define CREGU    2000.0f

#define B        256
#define NQ       (NV / 4)                      // 250000 vertex quads
#define PRE_BLOCKS   ((HW / 4) / B)            // 1024
#define PROJ_BLOCKS  ((NQ + B - 1) / B)        // 977
#define NPAIR    (NE / 2)                      // 1500000 int4 edge-pairs
#define ETH      (NPAIR / 4)                   // 375000 edge threads (8 edges ea)
#define EDGE_BLOCKS  ((ETH + B - 1) / B)       // 1465
#define ENT      (HW / 8)                      // 131072 energy threads
#define EN_BLOCKS    (ENT / B)                 // 512

// ---------------- scratch (device globals; zero-initialized at load) --------
__device__ float    g_depth[HW];      // 4 MB    scatter-min target
__device__ float4   g_dv4[NV];        // 16 MB   {dvx, dvy, dvz, 0}
__device__ float4   g_neigh4[NV];     // 16 MB   {nx, ny, nz, deg}
__device__ double   g_sums[3];        // vertex component sums (self-zeroing)
__device__ double   g_acc;            // total energy accumulator (self-zeroing)
__device__ unsigned g_done;           // last-block counter (self-zeroing)

// ---------------- float block reduce (shared) --------------------------------
__device__ __forceinline__ float block_reduce_f(float v) {
    __shared__ float sh[B];
    int t = threadIdx.x;
    sh[t] = v;
    __syncthreads();
    for (int s = blockDim.x >> 1; s > 32; s >>= 1) {
        if (t < s) sh[t] += sh[t + s];
        __syncthreads();
    }
    if (t < 32) {
        float x = sh[t] + sh[t + 32];
        #pragma unroll
        for (int o = 16; o > 0; o >>= 1)
            x += __shfl_down_sync(0xFFFFFFFFu, x, o);
        if (t == 0) sh[0] = x;
    }
    __syncthreads();
    return sh[0];
}

// ---------------- K1: depth fill + vertex mean partials ----------------------
// MUST complete before any atomicMin on g_depth (separate launch = ordered).
__global__ void k_mean_fill(const float4* __restrict__ verts4) {
    int i = blockIdx.x * blockDim.x + threadIdx.x;   // < 262144
    ((float4*)g_depth)[i] = make_float4(MAX_DEPTH, MAX_DEPTH, MAX_DEPTH, MAX_DEPTH);

    float sx = 0.0f, sy = 0.0f, sz = 0.0f;
    if (i < NQ) {
        float4 a = verts4[3 * i + 0];   // v0.x v0.y v0.z v1.x
        float4 b = verts4[3 * i + 1];   // v1.y v1.z v2.x v2.y
        float4 c = verts4[3 * i + 2];   // v2.z v3.x v3.y v3.z
        sx = a.x + a.w + b.z + c.y;
        sy = a.y + b.x + b.w + c.z;
        sz = a.z + b.y + c.x + c.w;
    }
    float bx = block_reduce_f(sx);
    __syncthreads();
    float by = block_reduce_f(sy);
    __syncthreads();
    float bz = block_reduce_f(sz);
    if (threadIdx.x == 0) {
        atomicAdd(&g_sums[0], (double)bx);
        atomicAdd(&g_sums[1], (double)by);
        atomicAdd(&g_sums[2], (double)bz);
    }
}

// ---------------- K2: dv + neigh zero + project (verts read once) ------------
__global__ void k_pre_proj(const float4* __restrict__ verts4,
                           const float4* __restrict__ vref4,
                           const float* __restrict__ quat,
                           const float* __restrict__ trans,
                           const float* __restrict__ intr,
                           const float* __restrict__ extr) {
    int i = blockIdx.x * blockDim.x + threadIdx.x;   // < 250000
    if (i >= NQ) return;

    float4 a = verts4[3 * i + 0];
    float4 b = verts4[3 * i + 1];
    float4 c = verts4[3 * i + 2];
    float4 ra = vref4[3 * i + 0];
    float4 rb = vref4[3 * i + 1];
    float4 rc = vref4[3 * i + 2];

    g_dv4[4 * i + 0] = make_float4(a.x - ra.x, a.y - ra.y, a.z - ra.z, 0.0f);
    g_dv4[4 * i + 1] = make_float4(a.w - ra.w, b.x - rb.x, b.y - rb.y, 0.0f);
    g_dv4[4 * i + 2] = make_float4(b.z - rb.z, b.w - rb.w, c.x - rc.x, 0.0f);
    g_dv4[4 * i + 3] = make_float4(c.y - rc.y, c.z - rc.z, c.w - rc.w, 0.0f);
    float4 z4 = make_float4(0.0f, 0.0f, 0.0f, 0.0f);
    g_neigh4[4 * i + 0] = z4;
    g_neigh4[4 * i + 1] = z4;
    g_neigh4[4 * i + 2] = z4;
    g_neigh4[4 * i + 3] = z4;

    // ---- projection (mean ready from K1; depth filled by K1) ----
    float qx = quat[0], qy = quat[1], qz = quat[2], qw = quat[3];
    float qn = 1.0f / sqrtf(qx * qx + qy * qy + qz * qz + qw * qw);
    qx *= qn; qy *= qn; qz *= qn; qw *= qn;

    float mx = (float)(g_sums[0] / (double)NV);
    float my = (float)(g_sums[1] / (double)NV);
    float mz = (float)(g_sums[2] / (double)NV);

    float vxs[4] = {a.x, a.w, b.z, c.y};
    float vys[4] = {a.y, b.x, b.w, c.z};
    float vzs[4] = {a.z, b.y, c.x, c.w};

    #pragma unroll
    for (int k = 0; k < 4; k++) {
        float vx = vxs[k] - mx;
        float vy = vys[k] - my;
        float vz = vzs[k] - mz;

        // qrot: v + 2*(w*uv + uuv), uv = qv x v, uuv = qv x uv
        float uvx = qy * vz - qz * vy;
        float uvy = qz * vx - qx * vz;
        float uvz = qx * vy - qy * vx;
        float uuvx = qy * uvz - qz * uvy;
        float uuvy = qz * uvx - qx * uvz;
        float uuvz = qx * uvy - qy * uvx;
        float tx = vx + 2.0f * (qw * uvx + uuvx) + trans[0];
        float ty = vy + 2.0f * (qw * uvy + uuvy) + trans[1];
        float tz = vz + 2.0f * (qw * uvz + uuvz) + trans[2];

        // p_cam = E[:, :3] @ v_t + E[:, 3]   (extr row-major 3x4)
        float p0 = extr[0] * tx + extr[1] * ty + extr[2]  * tz + extr[3];
        float p1 = extr[4] * tx + extr[5] * ty + extr[6]  * tz + extr[7];
        float p2 = extr[8] * tx + extr[9] * ty + extr[10] * tz + extr[11];

        // proj = K @ p_cam (intr row-major 3x3)
        float pr0 = intr[0] * p0 + intr[1] * p1 + intr[2] * p2;
        float pr1 = intr[3] * p0 + intr[4] * p1 + intr[5] * p2;
        float pr2 = intr[6] * p0 + intr[7] * p1 + intr[8] * p2;

        float u = pr0 / pr2;
        float v = pr1 / pr2;

        float fx = rintf(u);                  // round half to even == jnp.round
        float fy = rintf(v);
        fx = fminf(fmaxf(fx, 0.0f), (float)(IMG_W - 1));
        fy = fminf(fmaxf(fy, 0.0f), (float)(IMG_H - 1));
        int flat = (int)fy * IMG_W + (int)fx;

        float zval = (p2 > 0.0f) ? p2 : MAX_DEPTH;   // DEPTH_SCALE = 1
        // zval > 0, so int-bitpattern min == float min
        atomicMin((int*)&g_depth[flat], __float_as_int(zval));
    }
}

// ---------------- K3: edge accumulation, 8 edges/thread (MLP=8 gathers) -----
__global__ void k_edge(const int4* __restrict__ edges2) {
    int e = blockIdx.x * blockDim.x + threadIdx.x;   // < ETH = 375000
    if (e >= ETH) return;

    // 4 grid-strided coalesced int4 loads = 8 edges
    int4 p0 = edges2[e];
    int4 p1 = edges2[e + ETH];
    int4 p2 = edges2[e + 2 * ETH];
    int4 p3 = edges2[e + 3 * ETH];

    // 8 independent gathers in flight
    float4 d0 = g_dv4[p0.y];
    float4 d1 = g_dv4[p0.w];
    float4 d2 = g_dv4[p1.y];
    float4 d3 = g_dv4[p1.w];
    float4 d4 = g_dv4[p2.y];
    float4 d5 = g_dv4[p2.w];
    float4 d6 = g_dv4[p3.y];
    float4 d7 = g_dv4[p3.w];

    #define RED4(dst, dv)                                                     \
        asm volatile("red.global.add.v4.f32 [%0], {%1, %2, %3, %4};"          \
            :: "l"(&g_neigh4[dst]), "f"((dv).x), "f"((dv).y), "f"((dv).z),    \
               "f"(1.0f) : "memory")
    RED4(p0.x, d0);
    RED4(p0.z, d1);
    RED4(p1.x, d2);
    RED4(p1.z, d3);
    RED4(p2.x, d4);
    RED4(p2.z, d5);
    RED4(p3.x, d6);
    RED4(p3.z, d7);
    #undef RED4
}

// ---------------- K4: energy + last-block finalize (2x unrolled) -------------
__global__ void k_energy_final(const float4* __restrict__ hand4,
                               float* __restrict__ out) {
    int i = blockIdx.x * blockDim.x + threadIdx.x;   // < ENT = 131072
    float local = 0.0f;

    // two independent pixel-quad iterations
    float4 da = ((const float4*)g_depth)[i];
    float4 ha = hand4[i];
    float4 db = ((const float4*)g_depth)[i + ENT];
    float4 hb = hand4[i + ENT];
    float a0 = da.x - ha.x, a1 = da.y - ha.y, a2 = da.z - ha.z, a3 = da.w - ha.w;
    float b0 = db.x - hb.x, b1 = db.y - hb.y, b2 = db.z - hb.z, b3 = db.w - hb.w;
    local = a0 * a0 + a1 * a1 + a2 * a2 + a3 * a3
          + b0 * b0 + b1 * b1 + b2 * b2 + b3 * b3;

    // two vertex-quad iterations: j = i (always < NQ) and j = i + ENT
    #pragma unroll
    for (int r = 0; r < 2; r++) {
        int j = i + r * ENT;
        if (j < NQ) {
            #pragma unroll
            for (int k = 0; k < 4; k++) {
                float4 dv = g_dv4[4 * j + k];
                float4 nb = g_neigh4[4 * j + k];
                float dg = nb.w;
                float lx = dg * dv.x - nb.x;
                float ly = dg * dv.y - nb.y;
                float lz = dg * dv.z - nb.z;
                local += CREGU * (lx * lx + ly * ly + lz * lz);
            }
        }
    }
    float b = block_reduce_f(local);
    if (threadIdx.x == 0) {
        atomicAdd(&g_acc, (double)b);
        __threadfence();
        unsigned t = atomicAdd(&g_done, 1u);
        if (t == gridDim.x - 1) {      // last block: finalize + re-zero
            out[0] = (float)g_acc;
            g_acc = 0.0;
            g_sums[0] = 0.0; g_sums[1] = 0.0; g_sums[2] = 0.0;
            g_done = 0u;
        }
    }
}

// ---------------- launch -----------------------------------------------------
extern "C" void kernel_launch(void* const* d_in, const int* in_sizes, int n_in,
                              void* d_out, int out_size) {
    const float4* verts4 = (const float4*)d_in[0];
    const float4* vref4  = (const float4*)d_in[1];
    const float*  quat   = (const float*)d_in[2];
    const float*  trans  = (const float*)d_in[3];
    const float4* hand4  = (const float4*)d_in[4];
    const float*  intr   = (const float*)d_in[5];
    const float*  extr   = (const float*)d_in[6];
    const int4*   edges2 = (const int4*)d_in[7];
    float* out = (float*)d_out;

    k_mean_fill<<<PRE_BLOCKS, B>>>(verts4);
    k_pre_proj<<<PROJ_BLOCKS, B>>>(verts4, vref4, quat, trans, intr, extr);
    k_edge<<<EDGE_BLOCKS, B>>>(edges2);
    k_energy_final<<<EN_BLOCKS, B>>>(hand4, out);
}